// round 4
// baseline (speedup 1.0000x reference)
#include <cuda_runtime.h>

#define HW   512
#define TILE 32
#define RS   48   // raw tile (TILE + 2*8 halo)
#define MS   40   // intermediate (TILE + 2*4)
#define NTHREADS 256

__device__ __forceinline__ int refl(int i) {
    i = ::abs(i);
    return i < HW ? i : (2 * HW - 2 - i);
}

__device__ __forceinline__ float4 f4add(float4 a, float4 b) {
    return make_float4(a.x + b.x, a.y + b.y, a.z + b.z, a.w + b.w);
}
__device__ __forceinline__ float4 f4sub(float4 a, float4 b) {
    return make_float4(a.x - b.x, a.y - b.y, a.z - b.z, a.w - b.w);
}

// asinh(x) = sign(x) * log(|x| + sqrt(x^2+1)); sqrt via v*rsqrt(v) (v>=1)
__device__ __forceinline__ float fast_asinh(float x) {
    float ax = fabsf(x);
    float v  = fmaf(ax, ax, 1.0f);
    float s  = v * rsqrtf(v);
    float r  = __logf(ax + s);
    return copysignf(r, x);
}

__global__ __launch_bounds__(NTHREADS) void imgnorm_kernel(
    const float* __restrict__ img, const float* __restrict__ bg,
    const float* __restrict__ thr, const float* __restrict__ scl,
    float* __restrict__ out)
{
    __shared__ float sraw[RS][RS];     // raw with halo 8      (row = 192B)
    __shared__ float shs [RS][MS];     // hsum9 of raw         (row = 160B)
    __shared__ float sres[MS][MS];     // raw - boxmean(raw)   (row = 160B)
    __shared__ float shs2[MS][TILE];   // hsum9 of res^2       (row = 128B)

    const int bc  = blockIdx.z;            // b*5 + c
    const int tx0 = blockIdx.x * TILE;
    const int ty0 = blockIdx.y * TILE;
    const float* im  = img + (size_t)bc * HW * HW;
    const float* bgp = bg  + (size_t)bc * HW * HW;
    const int tid = threadIdx.x;
    const float inv81 = 1.0f / 81.0f;

    // Phase 1: load 48x48 raw tile. Interior blocks: vectorized LDG.128.
    const bool interior = (tx0 >= 8) && (tx0 + RS - 8 <= HW) &&
                          (ty0 >= 8) && (ty0 + RS - 8 <= HW);
    if (interior) {
        const float* base = im + (ty0 - 8) * HW + (tx0 - 8);
        for (int t = tid; t < RS * (RS / 4); t += NTHREADS) {   // 576 tasks
            int r = t / 12, c4 = (t - r * 12) * 4;
            *(float4*)&sraw[r][c4] = *(const float4*)&base[r * HW + c4];
        }
    } else {
        for (int i = tid; i < RS * RS; i += NTHREADS) {
            int r = i / RS, c = i - r * RS;
            sraw[r][c] = im[refl(ty0 + r - 8) * HW + refl(tx0 + c - 8)];
        }
    }
    __syncthreads();

    // Phase 2: horizontal 9-sums of raw, 48 rows x 40 cols (4 outs/task)
    for (int t = tid; t < RS * (MS / 4); t += NTHREADS) {   // 480 tasks
        int r = t / 10, c4 = (t - r * 10) * 4;
        float4 a = *(const float4*)&sraw[r][c4];
        float4 b = *(const float4*)&sraw[r][c4 + 4];
        float4 c = *(const float4*)&sraw[r][c4 + 8];
        float s0 = ((a.x + a.y) + (a.z + a.w)) + ((b.x + b.y) + (b.z + b.w)) + c.x;
        float s1 = s0 - a.x + c.y;
        float s2 = s1 - a.y + c.z;
        float s3 = s2 - a.z + c.w;
        *(float4*)&shs[r][c4] = make_float4(s0, s1, s2, s3);
    }
    __syncthreads();

    // Phase 3: vertical 9-sums -> mean -> res, 40x40.
    // float4 across columns, 2-row sliding groups: 20 rgroups x 10 col4 = 200 tasks.
    for (int t = tid; t < (MS / 2) * (MS / 4); t += NTHREADS) {
        int rg = t / 10, c4 = (t - rg * 10) * 4;
        int r0 = rg * 2;
        float4 w0 = *(const float4*)&shs[r0][c4];
        float4 s  = w0;
        #pragma unroll
        for (int k = 1; k < 9; k++)
            s = f4add(s, *(const float4*)&shs[r0 + k][c4]);
        float4 rv = *(const float4*)&sraw[r0 + 4][c4 + 4];
        *(float4*)&sres[r0][c4] = make_float4(
            rv.x - s.x * inv81, rv.y - s.y * inv81,
            rv.z - s.z * inv81, rv.w - s.w * inv81);
        float4 w9 = *(const float4*)&shs[r0 + 9][c4];
        s  = f4add(s, f4sub(w9, w0));
        rv = *(const float4*)&sraw[r0 + 5][c4 + 4];
        *(float4*)&sres[r0 + 1][c4] = make_float4(
            rv.x - s.x * inv81, rv.y - s.y * inv81,
            rv.z - s.z * inv81, rv.w - s.w * inv81);
    }
    __syncthreads();

    // Phase 4: horizontal 9-sums of res^2, 40 rows x 32 cols (4 outs/task)
    for (int t = tid; t < MS * (TILE / 4); t += NTHREADS) { // 320 tasks
        int r = t >> 3, c4 = (t & 7) * 4;
        float4 a = *(const float4*)&sres[r][c4];
        float4 b = *(const float4*)&sres[r][c4 + 4];
        float4 c = *(const float4*)&sres[r][c4 + 8];
        float q0 = a.x*a.x, q1 = a.y*a.y, q2 = a.z*a.z, q3 = a.w*a.w;
        float q4 = b.x*b.x, q5 = b.y*b.y, q6 = b.z*b.z, q7 = b.w*b.w;
        float q8 = c.x*c.x, q9 = c.y*c.y, q10 = c.z*c.z, q11 = c.w*c.w;
        float s0 = ((q0 + q1) + (q2 + q3)) + ((q4 + q5) + (q6 + q7)) + q8;
        float s1 = s0 - q0 + q9;
        float s2 = s1 - q1 + q10;
        float s3 = s2 - q2 + q11;
        *(float4*)&shs2[r][c4] = make_float4(s0, s1, s2, s3);
    }
    __syncthreads();

    // Per-channel asinh constants (broadcast loads)
    const int cb = bc % 5;
    const float th0 = thr[cb * 3 + 0], th1 = thr[cb * 3 + 1], th2 = thr[cb * 3 + 2];
    const float sc0 = __expf(scl[cb * 3 + 0]);
    const float sc1 = __expf(scl[cb * 3 + 1]);
    const float sc2 = __expf(scl[cb * 3 + 2]);

    // Phase 5: row-wise, 4 adjacent pixels per thread — everything float4.
    const int row = tid >> 3;          // 0..31
    const int c4  = (tid & 7) << 2;    // 0..28
    const int gy  = ty0 + row;
    const int gx0 = tx0 + c4;
    const size_t CH = (size_t)HW * HW;
    const size_t p  = (size_t)bc * 7 * CH + (size_t)gy * HW + gx0;

    // Vertical 9-sum of shs2 (float4 across 9 rows)
    float4 v = *(const float4*)&shs2[row][c4];
    #pragma unroll
    for (int d = 1; d < 9; d++)
        v = f4add(v, *(const float4*)&shs2[row + d][c4]);

    float raw[4], res[4], bgv[4], vv[4];
    *(float4*)raw = *(const float4*)&sraw[row + 8][c4 + 8];
    *(float4*)res = *(const float4*)&sres[row + 4][c4 + 4];
    *(float4*)bgv = *(const float4*)&bgp[(size_t)gy * HW + gx0];
    *(float4*)vv  = v;

    float l0[4], l1[4], cl[4], a0[4], a1[4], a2[4];
    #pragma unroll
    for (int j = 0; j < 4; j++) {
        float m = vv[j] * inv81;
        cl[j] = res[j] * rsqrtf(fmaxf(m, 1.0f));
        float off = (raw[j] - bgv[j]) * rsqrtf(bgv[j]);
        l0[j] = __logf(fmaxf(off + 1.0f, 1.0f));
        l1[j] = __logf(fmaxf(off,        1.0f));
        a0[j] = fast_asinh((raw[j] - th0) * sc0);
        a1[j] = fast_asinh((raw[j] - th1) * sc1);
        a2[j] = fast_asinh((raw[j] - th2) * sc2);
    }

    // Streaming stores: output is write-once, keep L2 for input halo reuse.
    __stcs((float4*)&out[p],          *(float4*)raw);
    __stcs((float4*)&out[p + 1 * CH], *(float4*)l0);
    __stcs((float4*)&out[p + 2 * CH], *(float4*)l1);
    __stcs((float4*)&out[p + 3 * CH], *(float4*)cl);
    __stcs((float4*)&out[p + 4 * CH], *(float4*)a0);
    __stcs((float4*)&out[p + 5 * CH], *(float4*)a1);
    __stcs((float4*)&out[p + 6 * CH], *(float4*)a2);
}

extern "C" void kernel_launch(void* const* d_in, const int* in_sizes, int n_in,
                              void* d_out, int out_size) {
    const float* img = (const float*)d_in[0];
    const float* bg  = (const float*)d_in[1];
    const float* thr = (const float*)d_in[2];
    const float* scl = (const float*)d_in[3];
    float* out = (float*)d_out;
    dim3 grid(HW / TILE, HW / TILE, 8 * 5);
    imgnorm_kernel<<<grid, NTHREADS>>>(img, bg, thr, scl, out);
}

// round 5
// speedup vs baseline: 1.0650x; 1.0650x over previous
#include <cuda_runtime.h>

#define HW   512
#define TILE 32
#define RS   48   // raw tile (TILE + 2*8 halo)
#define MS   40   // intermediate (TILE + 2*4)
#define NTHREADS 256

__device__ __forceinline__ int refl(int i) {
    i = ::abs(i);
    return i < HW ? i : (2 * HW - 2 - i);
}

// asinh(x) = sign(x) * log(|x| + sqrt(x^2+1)); sqrt via v*rsqrt(v) (v>=1)
__device__ __forceinline__ float fast_asinh(float x) {
    float ax = fabsf(x);
    float v  = fmaf(ax, ax, 1.0f);
    float s  = v * rsqrtf(v);
    float r  = __logf(ax + s);
    return copysignf(r, x);
}

__global__ __launch_bounds__(NTHREADS) void imgnorm_kernel(
    const float* __restrict__ img, const float* __restrict__ bg,
    const float* __restrict__ thr, const float* __restrict__ scl,
    float* __restrict__ out)
{
    __shared__ float sraw [RS][RS];    // raw with halo 8      (row = 192B)
    __shared__ float shs  [RS][MS];    // hsum9 of raw         (row = 160B)
    __shared__ float sres [MS][MS];    // raw - boxmean(raw)   (row = 160B)
    __shared__ float shs2 [MS][TILE];  // hsum9 of res^2       (row = 128B)
    __shared__ float sbox2[TILE][TILE];// vsum9 of shs2        (row = 128B)

    const int bc  = blockIdx.z;            // b*5 + c
    const int tx0 = blockIdx.x * TILE;
    const int ty0 = blockIdx.y * TILE;
    const float* im  = img + (size_t)bc * HW * HW;
    const float* bgp = bg  + (size_t)bc * HW * HW;
    const int tid = threadIdx.x;
    const float inv81 = 1.0f / 81.0f;

    // Phase 1: load 48x48 raw tile. Interior blocks: vectorized LDG.128.
    const bool interior = (tx0 >= 8) && (tx0 + RS - 8 <= HW) &&
                          (ty0 >= 8) && (ty0 + RS - 8 <= HW);
    if (interior) {
        const float* base = im + (ty0 - 8) * HW + (tx0 - 8);
        for (int t = tid; t < RS * (RS / 4); t += NTHREADS) {   // 576 tasks
            int r = t / 12, c4 = (t - r * 12) * 4;
            *(float4*)&sraw[r][c4] = *(const float4*)&base[r * HW + c4];
        }
    } else {
        for (int i = tid; i < RS * RS; i += NTHREADS) {
            int r = i / RS, c = i - r * RS;
            sraw[r][c] = im[refl(ty0 + r - 8) * HW + refl(tx0 + c - 8)];
        }
    }
    __syncthreads();

    // Phase 2: horizontal 9-sums of raw, 48 rows x 40 cols (4 outs/task, float4)
    for (int t = tid; t < RS * (MS / 4); t += NTHREADS) {   // 480 tasks
        int r = t / 10, c4 = (t - r * 10) * 4;
        float4 a = *(const float4*)&sraw[r][c4];
        float4 b = *(const float4*)&sraw[r][c4 + 4];
        float4 c = *(const float4*)&sraw[r][c4 + 8];
        float s0 = ((a.x + a.y) + (a.z + a.w)) + ((b.x + b.y) + (b.z + b.w)) + c.x;
        float s1 = s0 - a.x + c.y;
        float s2 = s1 - a.y + c.z;
        float s3 = s2 - a.z + c.w;
        *(float4*)&shs[r][c4] = make_float4(s0, s1, s2, s3);
    }
    __syncthreads();

    // Phase 3: vertical 9-sums -> mean -> res, 40x40.
    // Column ownership, 4-row register sliding window (scalar = min crossbar bytes).
    for (int t = tid; t < (MS / 4) * MS; t += NTHREADS) {   // 400 tasks
        int rg = t / MS, c = t - rg * MS;
        int r0 = rg * 4;
        float w[12];
        #pragma unroll
        for (int k = 0; k < 12; k++) w[k] = shs[r0 + k][c];
        float s = ((w[0] + w[1]) + (w[2] + w[3])) + ((w[4] + w[5]) + (w[6] + w[7])) + w[8];
        sres[r0 + 0][c] = sraw[r0 + 4][c + 4] - s * inv81;
        s += w[9]  - w[0];
        sres[r0 + 1][c] = sraw[r0 + 5][c + 4] - s * inv81;
        s += w[10] - w[1];
        sres[r0 + 2][c] = sraw[r0 + 6][c + 4] - s * inv81;
        s += w[11] - w[2];
        sres[r0 + 3][c] = sraw[r0 + 7][c + 4] - s * inv81;
    }
    __syncthreads();

    // Phase 4: horizontal 9-sums of res^2, 40 rows x 32 cols (4 outs/task, float4)
    for (int t = tid; t < MS * (TILE / 4); t += NTHREADS) { // 320 tasks
        int r = t >> 3, c4 = (t & 7) * 4;
        float4 a = *(const float4*)&sres[r][c4];
        float4 b = *(const float4*)&sres[r][c4 + 4];
        float4 c = *(const float4*)&sres[r][c4 + 8];
        float q0 = a.x*a.x, q1 = a.y*a.y, q2 = a.z*a.z, q3 = a.w*a.w;
        float q4 = b.x*b.x, q5 = b.y*b.y, q6 = b.z*b.z, q7 = b.w*b.w;
        float q8 = c.x*c.x, q9 = c.y*c.y, q10 = c.z*c.z, q11 = c.w*c.w;
        float s0 = ((q0 + q1) + (q2 + q3)) + ((q4 + q5) + (q6 + q7)) + q8;
        float s1 = s0 - q0 + q9;
        float s2 = s1 - q1 + q10;
        float s3 = s2 - q2 + q11;
        *(float4*)&shs2[r][c4] = make_float4(s0, s1, s2, s3);
    }
    __syncthreads();

    // Phase 4.5: vertical 9-sum of shs2 -> sbox2, 32x32.
    // Exactly 1 task/thread: column ownership, 4-row register sliding.
    {
        int c  = tid & 31;
        int r0 = (tid >> 5) * 4;
        float w[12];
        #pragma unroll
        for (int k = 0; k < 12; k++) w[k] = shs2[r0 + k][c];
        float s = ((w[0] + w[1]) + (w[2] + w[3])) + ((w[4] + w[5]) + (w[6] + w[7])) + w[8];
        sbox2[r0 + 0][c] = s;
        s += w[9]  - w[0];
        sbox2[r0 + 1][c] = s;
        s += w[10] - w[1];
        sbox2[r0 + 2][c] = s;
        s += w[11] - w[2];
        sbox2[r0 + 3][c] = s;
    }
    __syncthreads();

    // Per-channel asinh constants (broadcast loads)
    const int cb = bc % 5;
    const float th0 = thr[cb * 3 + 0], th1 = thr[cb * 3 + 1], th2 = thr[cb * 3 + 2];
    const float sc0 = __expf(scl[cb * 3 + 0]);
    const float sc1 = __expf(scl[cb * 3 + 1]);
    const float sc2 = __expf(scl[cb * 3 + 2]);

    // Phase 5: row-wise, 4 adjacent pixels per thread — everything float4.
    const int row = tid >> 3;          // 0..31
    const int c4  = (tid & 7) << 2;    // 0..28
    const int gy  = ty0 + row;
    const int gx0 = tx0 + c4;
    const size_t CH = (size_t)HW * HW;
    const size_t p  = (size_t)bc * 7 * CH + (size_t)gy * HW + gx0;

    float raw[4], res[4], bgv[4], vv[4];
    *(float4*)raw = *(const float4*)&sraw [row + 8][c4 + 8];
    *(float4*)res = *(const float4*)&sres [row + 4][c4 + 4];
    *(float4*)vv  = *(const float4*)&sbox2[row][c4];
    *(float4*)bgv = *(const float4*)&bgp[(size_t)gy * HW + gx0];

    float l0[4], l1[4], cl[4], a0[4], a1[4], a2[4];
    #pragma unroll
    for (int j = 0; j < 4; j++) {
        float m = vv[j] * inv81;
        cl[j] = res[j] * rsqrtf(fmaxf(m, 1.0f));
        float off = (raw[j] - bgv[j]) * rsqrtf(bgv[j]);
        l0[j] = __logf(fmaxf(off + 1.0f, 1.0f));
        l1[j] = __logf(fmaxf(off,        1.0f));
        a0[j] = fast_asinh((raw[j] - th0) * sc0);
        a1[j] = fast_asinh((raw[j] - th1) * sc1);
        a2[j] = fast_asinh((raw[j] - th2) * sc2);
    }

    *(float4*)&out[p]          = *(float4*)raw;
    *(float4*)&out[p + 1 * CH] = *(float4*)l0;
    *(float4*)&out[p + 2 * CH] = *(float4*)l1;
    *(float4*)&out[p + 3 * CH] = *(float4*)cl;
    *(float4*)&out[p + 4 * CH] = *(float4*)a0;
    *(float4*)&out[p + 5 * CH] = *(float4*)a1;
    *(float4*)&out[p + 6 * CH] = *(float4*)a2;
}

extern "C" void kernel_launch(void* const* d_in, const int* in_sizes, int n_in,
                              void* d_out, int out_size) {
    const float* img = (const float*)d_in[0];
    const float* bg  = (const float*)d_in[1];
    const float* thr = (const float*)d_in[2];
    const float* scl = (const float*)d_in[3];
    float* out = (float*)d_out;
    dim3 grid(HW / TILE, HW / TILE, 8 * 5);
    imgnorm_kernel<<<grid, NTHREADS>>>(img, bg, thr, scl, out);
}